// round 11
// baseline (speedup 1.0000x reference)
#include <cuda_runtime.h>
#include <cstdint>

// Problem constants
#define S_LEN   64
#define D_MODEL 768
#define D_FFN   3072
#define RANK    16
#define MOD_SCALE 0.1f

// Packed f32x2 ops (ptxas won't auto-fuse from C++).
#define FMA_F32X2(d, a, b, c) \
    asm("fma.rn.f32x2 %0, %1, %2, %3;" : "=l"(d) : "l"(a), "l"(b), "l"(c))
#define ADD_F32X2(d, a, b) \
    asm("add.rn.f32x2 %0, %1, %2;" : "=l"(d) : "l"(a), "l"(b))
// Duplicate a scalar float into a packed {s,s} 64-bit operand.
#define DUP_F32X2(d, s) \
    asm("mov.b64 %0, {%1, %1};" : "=l"(d) : "r"(__float_as_uint(s)))

// Scratch: modulation (64 x 16) + work-stealing counter. Device globals.
__device__ float    g_mod[S_LEN * RANK];
__device__ unsigned g_ctr;

// ---------------------------------------------------------------------------
// Kernel 1: modulation[s][r] = 0.1 * tanh( sum_d attn[s][d] * A[d][r] )
// Warp-per-output; also resets the work counter for the deltaw launch.
// ---------------------------------------------------------------------------
__global__ __launch_bounds__(256)
void mod_kernel(const float* __restrict__ attn,
                const float* __restrict__ A)
{
    if (blockIdx.x == 0 && threadIdx.x == 0) g_ctr = 0u;

    const int gw  = blockIdx.x * 8 + (threadIdx.x >> 5);  // 0..1023
    const int lid = threadIdx.x & 31;
    const int s   = gw >> 4;
    const int r   = gw & 15;

    const float* arow = attn + (size_t)s * D_MODEL;
    float acc = 0.0f;
#pragma unroll
    for (int k = 0; k < D_MODEL / 32; k++) {              // 24 iterations
        const int d = lid + 32 * k;
        acc += arow[d] * A[d * RANK + r];
    }
#pragma unroll
    for (int off = 16; off > 0; off >>= 1)
        acc += __shfl_down_sync(0xFFFFFFFFu, acc, off);

    if (lid == 0) g_mod[s * RANK + r] = MOD_SCALE * tanhf(acc);
}

// ---------------------------------------------------------------------------
// Kernel 2: delta_w[p][f] = sum_r C[p][r] * B[r][f]
//
// RANK-SPLIT layout: lane pair (2t, 2t+1) owns 4 consecutive f; the even
// lane accumulates r=0..7, the odd lane r=8..15. B slab per thread is only
// 8 x ulonglong2 = 32 regs -> ~60 regs total -> 4 CTAs/SM (32 warps).
// Per pair per thread: 2 LDS.128 + 8 dup + 16 FFMA2, then one 64-bit
// shfl.xor(1) exchanges cross-half partials (even lane finalizes {f0,f1},
// odd lane {f2,f3}), one packed add, one coalesced streaming STG.64.
// Persistent work-stealing with claim-ahead; one s per 64-pair chunk.
// ---------------------------------------------------------------------------
#define FTILE        512
#define PAIRS_PER_CH 64
#define THREADS      256
#define N_PCHUNK     ((S_LEN * D_MODEL) / PAIRS_PER_CH)   // 768
#define N_ITEMS      (N_PCHUNK * (D_FFN / FTILE))         // 4608
#define GRID_BLOCKS  592                                  // 4 CTAs/SM x 148

__global__ __launch_bounds__(THREADS, 4)
void deltaw_kernel(const float* __restrict__ A,
                   const float* __restrict__ B,
                   float* __restrict__ out)
{
    __shared__ float    Cs[PAIRS_PER_CH][RANK];
    __shared__ unsigned s_claim;

    const int q   = threadIdx.x >> 1;       // 0..127: f-group index
    const int par = threadIdx.x & 1;        // 0: r0-7,f0-1  1: r8-15,f2-3

    ulonglong2 Breg[8];                     // 32 regs: my r-half x 4 f
    int prev_ftile = -1;

    if (threadIdx.x == 0) s_claim = atomicAdd(&g_ctr, 1u);
    __syncthreads();

    for (;;) {
        const unsigned idx = s_claim;
        if (idx >= N_ITEMS) break;

        // Claim-ahead: issue next atomic now, publish after compute.
        unsigned next_claim = 0u;
        if (threadIdx.x == 0) next_claim = atomicAdd(&g_ctr, 1u);

        const int ftile = (int)(idx / N_PCHUNK);          // 0..5
        const int pair0 = (int)(idx % N_PCHUNK) * PAIRS_PER_CH;
        const int f0    = ftile * FTILE + q * 4;          // pair-group base

        if (ftile != prev_ftile) {
            prev_ftile = ftile;
#pragma unroll
            for (int j = 0; j < 8; j++) {
                Breg[j] = *reinterpret_cast<const ulonglong2*>(
                    &B[(par * 8 + j) * D_FFN + f0]);
            }
        }

        // C build: one s per chunk (64 divides 768). Thread builds 4 entries
        // (pair p = tid/4, r-quad rq = tid%4) with float4 math, one STS.128.
        {
            const int s  = pair0 / D_MODEL;
            const int d0 = pair0 % D_MODEL;
            const int p  = threadIdx.x >> 2;
            const int rq = threadIdx.x & 3;
            const float4 m4 = *reinterpret_cast<const float4*>(&g_mod[s * RANK + rq * 4]);
            const float4 a4 = *reinterpret_cast<const float4*>(&A[(d0 + p) * RANK + rq * 4]);
            float4 c4;
            c4.x = m4.x * a4.x;  c4.y = m4.y * a4.y;
            c4.z = m4.z * a4.z;  c4.w = m4.w * a4.w;
            *reinterpret_cast<float4*>(&Cs[p][rq * 4]) = c4;
        }
        __syncthreads();

        float* outp = out + (size_t)pair0 * D_FFN + f0 + par * 2;
#pragma unroll 1
        for (int p = 0; p < PAIRS_PER_CH; p++) {
            const float4* cp = reinterpret_cast<const float4*>(&Cs[p][0]);
            const float4 cA = cp[par * 2];        // my r-half, quad 0
            const float4 cB = cp[par * 2 + 1];    // my r-half, quad 1

            uint64_t a0 = 0ull;   // partial accum for {f0, f0+1}
            uint64_t a1 = 0ull;   // partial accum for {f0+2, f0+3}
            uint64_t t0, t1, t2, t3;

            DUP_F32X2(t0, cA.x); DUP_F32X2(t1, cA.y);
            DUP_F32X2(t2, cA.z); DUP_F32X2(t3, cA.w);
            FMA_F32X2(a0, t0, Breg[0].x, a0);  FMA_F32X2(a1, t0, Breg[0].y, a1);
            FMA_F32X2(a0, t1, Breg[1].x, a0);  FMA_F32X2(a1, t1, Breg[1].y, a1);
            FMA_F32X2(a0, t2, Breg[2].x, a0);  FMA_F32X2(a1, t2, Breg[2].y, a1);
            FMA_F32X2(a0, t3, Breg[3].x, a0);  FMA_F32X2(a1, t3, Breg[3].y, a1);

            DUP_F32X2(t0, cB.x); DUP_F32X2(t1, cB.y);
            DUP_F32X2(t2, cB.z); DUP_F32X2(t3, cB.w);
            FMA_F32X2(a0, t0, Breg[4].x, a0);  FMA_F32X2(a1, t0, Breg[4].y, a1);
            FMA_F32X2(a0, t1, Breg[5].x, a0);  FMA_F32X2(a1, t1, Breg[5].y, a1);
            FMA_F32X2(a0, t2, Breg[6].x, a0);  FMA_F32X2(a1, t2, Breg[6].y, a1);
            FMA_F32X2(a0, t3, Breg[7].x, a0);  FMA_F32X2(a1, t3, Breg[7].y, a1);

            // Exchange cross-half partials with the partner lane:
            // even lane keeps {f0,f1} (needs partner's a0); odd keeps {f2,f3}.
            const unsigned long long send = par ? a0 : a1;
            const unsigned long long recv =
                __shfl_xor_sync(0xFFFFFFFFu, send, 1);
            const uint64_t mine = par ? a1 : a0;
            uint64_t res;
            ADD_F32X2(res, mine, (uint64_t)recv);

            float2 v;
            v.x = __uint_as_float((uint32_t)(res & 0xFFFFFFFFull));
            v.y = __uint_as_float((uint32_t)(res >> 32));
            __stcs(reinterpret_cast<float2*>(outp), v);   // streaming STG.64
            outp += D_FFN;
        }

        if (threadIdx.x == 0) s_claim = next_claim;
        __syncthreads();
    }
}

// ---------------------------------------------------------------------------
// Launch
// ---------------------------------------------------------------------------
extern "C" void kernel_launch(void* const* d_in, const int* in_sizes, int n_in,
                              void* d_out, int out_size)
{
    const float* attn = (const float*)d_in[0];  // (1, 64, 768)
    const float* A    = (const float*)d_in[1];  // (768, 16)
    const float* B    = (const float*)d_in[2];  // (16, 3072)
    float* out        = (float*)d_out;          // (1, 64, 768, 3072)

    mod_kernel<<<128, 256>>>(attn, A);
    deltaw_kernel<<<GRID_BLOCKS, THREADS>>>(A, B, out);
}

// round 12
// speedup vs baseline: 1.0635x; 1.0635x over previous
#include <cuda_runtime.h>
#include <cstdint>

// Problem constants
#define S_LEN   64
#define D_MODEL 768
#define D_FFN   3072
#define RANK    16
#define MOD_SCALE 0.1f

// Packed f32x2 ops (ptxas won't auto-fuse from C++).
#define FMA_F32X2(d, a, b, c) \
    asm("fma.rn.f32x2 %0, %1, %2, %3;" : "=l"(d) : "l"(a), "l"(b), "l"(c))
// Duplicate a scalar float into a packed {s,s} 64-bit operand.
#define DUP_F32X2(d, s) \
    asm("mov.b64 %0, {%1, %1};" : "=l"(d) : "r"(__float_as_uint(s)))

// Scratch: modulation (64 x 16) + work-stealing counter. Device globals.
__device__ float    g_mod[S_LEN * RANK];
__device__ unsigned g_ctr;

// ---------------------------------------------------------------------------
// Kernel 1: modulation[s][r] = 0.1 * tanh( sum_d attn[s][d] * A[d][r] )
// Warp-per-output; also resets the work counter for the deltaw launch.
// ---------------------------------------------------------------------------
__global__ __launch_bounds__(256)
void mod_kernel(const float* __restrict__ attn,
                const float* __restrict__ A)
{
    if (blockIdx.x == 0 && threadIdx.x == 0) g_ctr = 0u;

    const int gw  = blockIdx.x * 8 + (threadIdx.x >> 5);  // 0..1023
    const int lid = threadIdx.x & 31;
    const int s   = gw >> 4;
    const int r   = gw & 15;

    const float* arow = attn + (size_t)s * D_MODEL;
    float acc = 0.0f;
#pragma unroll
    for (int k = 0; k < D_MODEL / 32; k++) {              // 24 iterations
        const int d = lid + 32 * k;
        acc += arow[d] * A[d * RANK + r];
    }
#pragma unroll
    for (int off = 16; off > 0; off >>= 1)
        acc += __shfl_down_sync(0xFFFFFFFFu, acc, off);

    if (lid == 0) g_mod[s * RANK + r] = MOD_SCALE * tanhf(acc);
}

// ---------------------------------------------------------------------------
// Kernel 2: delta_w[p][f] = sum_r C[p][r] * B[r][f]
//
// R9 math core (non-dup C smem, mov.b64 dup, 2-chain packed FFMA2, B slab
// register-resident, persistent 444-block work-steal with claim-ahead), but
// the store path is moved OFF the per-warp LSU: each 8-pair sub-tile is
// written with conflict-free STS.128 into a double-buffered 32KB smem stage
// and drained to GMEM by cp.async.bulk (bulk_group) issued from one thread.
// STG.128 (12-cycle issue) -> STS.128 (~4) + TMA engine.
// ---------------------------------------------------------------------------
#define FTILE        1024
#define CHUNK_PAIRS  64
#define STAGE_PAIRS  8
#define N_STAGES     (CHUNK_PAIRS / STAGE_PAIRS)          // 8
#define STAGE_BYTES  (STAGE_PAIRS * FTILE * 4)            // 32768
#define THREADS      256
#define N_PCHUNK     ((S_LEN * D_MODEL) / CHUNK_PAIRS)    // 768
#define N_ITEMS      (N_PCHUNK * (D_FFN / FTILE))         // 2304
#define GRID_BLOCKS  444

__global__ __launch_bounds__(THREADS, 3)
void deltaw_kernel(const float* __restrict__ A,
                   const float* __restrict__ B,
                   float* __restrict__ out)
{
    extern __shared__ char stage_raw[];                   // 2 x 32KB stages
    __shared__ float    Cs[CHUNK_PAIRS][RANK];
    __shared__ unsigned s_claim;

    const unsigned stage_base =
        (unsigned)__cvta_generic_to_shared(stage_raw);

    ulonglong2 Breg[RANK];
    int prev_ftile = -1;
    int buf        = 0;

    if (threadIdx.x == 0) s_claim = atomicAdd(&g_ctr, 1u);
    __syncthreads();

    for (;;) {
        const unsigned idx = s_claim;
        if (idx >= N_ITEMS) break;

        // Claim-ahead: issue next atomic now, publish after compute.
        unsigned next_claim = 0u;
        if (threadIdx.x == 0) next_claim = atomicAdd(&g_ctr, 1u);

        const int ftile = (int)(idx / N_PCHUNK);          // 0..2
        const int pair0 = (int)(idx % N_PCHUNK) * CHUNK_PAIRS;
        const int f0    = ftile * FTILE + threadIdx.x * 4;

        if (ftile != prev_ftile) {
            prev_ftile = ftile;
#pragma unroll
            for (int r = 0; r < RANK; r++) {
                Breg[r] = *reinterpret_cast<const ulonglong2*>(&B[r * D_FFN + f0]);
            }
        }

        // C build: one s per 64-pair chunk (64 | 768): float4 math, 1 STS.128.
        {
            const int s  = pair0 / D_MODEL;
            const int d0 = pair0 % D_MODEL;
            const int p  = threadIdx.x >> 2;
            const int rq = threadIdx.x & 3;
            const float4 m4 = *reinterpret_cast<const float4*>(&g_mod[s * RANK + rq * 4]);
            const float4 a4 = *reinterpret_cast<const float4*>(&A[(d0 + p) * RANK + rq * 4]);
            float4 c4;
            c4.x = m4.x * a4.x;  c4.y = m4.y * a4.y;
            c4.z = m4.z * a4.z;  c4.w = m4.w * a4.w;
            *reinterpret_cast<float4*>(&Cs[p][rq * 4]) = c4;
        }
        __syncthreads();

#pragma unroll 1
        for (int st = 0; st < N_STAGES; st++) {
            // Wait until this buffer's previous bulk-group has drained.
            if (threadIdx.x == 0)
                asm volatile("cp.async.bulk.wait_group 1;" ::: "memory");
            __syncthreads();

            char* stg = stage_raw + buf * STAGE_BYTES + threadIdx.x * 16;

#pragma unroll 1
            for (int k = 0; k < STAGE_PAIRS; k++) {
                const int p = st * STAGE_PAIRS + k;
                const float4* cp = reinterpret_cast<const float4*>(&Cs[p][0]);
                uint64_t a0 = 0ull;   // packed accum for {f0, f0+1}
                uint64_t a1 = 0ull;   // packed accum for {f0+2, f0+3}
#pragma unroll
                for (int i = 0; i < 4; i++) {
                    const float4 c4 = cp[i];      // one broadcast LDS.128
                    uint64_t d0, d1, d2, d3;
                    DUP_F32X2(d0, c4.x);
                    DUP_F32X2(d1, c4.y);
                    DUP_F32X2(d2, c4.z);
                    DUP_F32X2(d3, c4.w);
                    FMA_F32X2(a0, d0, Breg[4 * i + 0].x, a0);
                    FMA_F32X2(a1, d0, Breg[4 * i + 0].y, a1);
                    FMA_F32X2(a0, d1, Breg[4 * i + 1].x, a0);
                    FMA_F32X2(a1, d1, Breg[4 * i + 1].y, a1);
                    FMA_F32X2(a0, d2, Breg[4 * i + 2].x, a0);
                    FMA_F32X2(a1, d2, Breg[4 * i + 2].y, a1);
                    FMA_F32X2(a0, d3, Breg[4 * i + 3].x, a0);
                    FMA_F32X2(a1, d3, Breg[4 * i + 3].y, a1);
                }
                float4 v;
                v.x = __uint_as_float((uint32_t)(a0 & 0xFFFFFFFFull));
                v.y = __uint_as_float((uint32_t)(a0 >> 32));
                v.z = __uint_as_float((uint32_t)(a1 & 0xFFFFFFFFull));
                v.w = __uint_as_float((uint32_t)(a1 >> 32));
                // Conflict-free STS.128 into the stage (thread t -> bytes 16t).
                *reinterpret_cast<float4*>(stg + k * (FTILE * 4)) = v;
            }
            __syncthreads();

            // One thread drains the stage: 8 rows x 4KB bulk copies.
            if (threadIdx.x == 0) {
                asm volatile("fence.proxy.async.shared::cta;" ::: "memory");
                const unsigned sb = stage_base + buf * STAGE_BYTES;
#pragma unroll
                for (int k = 0; k < STAGE_PAIRS; k++) {
                    const int p = st * STAGE_PAIRS + k;
                    float* gdst = out + (size_t)(pair0 + p) * D_FFN + ftile * FTILE;
                    asm volatile(
                        "cp.async.bulk.global.shared::cta.bulk_group [%0], [%1], %2;"
                        :: "l"(gdst), "r"(sb + k * (FTILE * 4)), "r"(FTILE * 4)
                        : "memory");
                }
                asm volatile("cp.async.bulk.commit_group;" ::: "memory");
            }
            buf ^= 1;
        }

        if (threadIdx.x == 0) s_claim = next_claim;
        __syncthreads();
    }

    // Drain all outstanding bulk stores before exit.
    if (threadIdx.x == 0)
        asm volatile("cp.async.bulk.wait_group 0;" ::: "memory");
}

// ---------------------------------------------------------------------------
// Launch
// ---------------------------------------------------------------------------
extern "C" void kernel_launch(void* const* d_in, const int* in_sizes, int n_in,
                              void* d_out, int out_size)
{
    const float* attn = (const float*)d_in[0];  // (1, 64, 768)
    const float* A    = (const float*)d_in[1];  // (768, 16)
    const float* B    = (const float*)d_in[2];  // (16, 3072)
    float* out        = (float*)d_out;          // (1, 64, 768, 3072)

    static bool attr_set = false;
    if (!attr_set) {
        cudaFuncSetAttribute(deltaw_kernel,
                             cudaFuncAttributeMaxDynamicSharedMemorySize,
                             2 * STAGE_BYTES);
        attr_set = true;
    }

    mod_kernel<<<128, 256>>>(attn, A);
    deltaw_kernel<<<GRID_BLOCKS, THREADS, 2 * STAGE_BYTES>>>(A, B, out);
}